// round 1
// baseline (speedup 1.0000x reference)
#include <cuda_runtime.h>

// ---------------------------------------------------------------------------
// FastSpatialWindowAttention: Swin-style window attention
//   B=4, H=W=256, C=192, NH=6, hd=32, WS=8 (no padding needed: 256 % 8 == 0)
// Pipeline:
//   1) qkv[tok, 576] = x[tok, 192] @ qkv_w^T           (token-major, window-free)
//   2) per (window, head): softmax(scale*QK^T + bias) V  -> att[tok, 192]
//   3) out[tok, 192] = att @ proj_w^T + proj_b
// ---------------------------------------------------------------------------

namespace {
constexpr int BATCH = 4;
constexpr int HIMG  = 256;
constexpr int WIMG  = 256;
constexpr int C     = 192;
constexpr int NH    = 6;
constexpr int HD    = 32;   // C / NH
constexpr int WS    = 8;
constexpr int WS2   = 64;
constexpr int LTOK  = HIMG * WIMG;          // 65536
constexpr int MTOK  = BATCH * LTOK;         // 262144
constexpr int QKVN  = 3 * C;                // 576
constexpr int NWIN  = BATCH * (HIMG / WS) * (WIMG / WS); // 4096
}

// Scratch (allocation-free rule: static device globals)
__device__ float g_qkv[(size_t)MTOK * QKVN]; // 604 MB
__device__ float g_att[(size_t)MTOK * C];    // 201 MB

// ---------------------------------------------------------------------------
// C[M,N] = A[M,K] @ W[N,K]^T (+ bias). M,N multiples of 64, K multiple of 16.
// 64x64 tile, BK=16, 256 threads, 4x4 per thread.
// ---------------------------------------------------------------------------
template<int BM, int BN, int BK>
__global__ __launch_bounds__(256)
void gemm_nt(const float* __restrict__ A,
             const float* __restrict__ W,
             const float* __restrict__ bias,
             float* __restrict__ Cout,
             int M, int N, int K)
{
    __shared__ float As[BK][BM + 1];
    __shared__ float Ws[BK][BN + 1];

    const int tid = threadIdx.x;
    const int tx  = tid & 15;
    const int ty  = tid >> 4;
    const int m0  = blockIdx.y * BM;
    const int n0  = blockIdx.x * BN;

    const int lrow = tid >> 2;       // 0..63
    const int lc4  = (tid & 3) * 4;  // 0,4,8,12

    float acc[4][4] = {};

    for (int k0 = 0; k0 < K; k0 += BK) {
        const float4 a4 = *reinterpret_cast<const float4*>(
            A + (size_t)(m0 + lrow) * K + k0 + lc4);
        const float4 w4 = *reinterpret_cast<const float4*>(
            W + (size_t)(n0 + lrow) * K + k0 + lc4);
        As[lc4 + 0][lrow] = a4.x; As[lc4 + 1][lrow] = a4.y;
        As[lc4 + 2][lrow] = a4.z; As[lc4 + 3][lrow] = a4.w;
        Ws[lc4 + 0][lrow] = w4.x; Ws[lc4 + 1][lrow] = w4.y;
        Ws[lc4 + 2][lrow] = w4.z; Ws[lc4 + 3][lrow] = w4.w;
        __syncthreads();

        #pragma unroll
        for (int k = 0; k < BK; ++k) {
            float a[4], b[4];
            #pragma unroll
            for (int i = 0; i < 4; ++i) a[i] = As[k][ty + i * 16];
            #pragma unroll
            for (int j = 0; j < 4; ++j) b[j] = Ws[k][tx + j * 16];
            #pragma unroll
            for (int i = 0; i < 4; ++i)
                #pragma unroll
                for (int j = 0; j < 4; ++j)
                    acc[i][j] += a[i] * b[j];
        }
        __syncthreads();
    }

    #pragma unroll
    for (int i = 0; i < 4; ++i) {
        const int m = m0 + ty + i * 16;
        #pragma unroll
        for (int j = 0; j < 4; ++j) {
            const int n = n0 + tx + j * 16;
            float v = acc[i][j];
            if (bias) v += bias[n];
            Cout[(size_t)m * N + n] = v;
        }
    }
}

// ---------------------------------------------------------------------------
// Window attention: one block per (window, head), 64 threads = 1 per query row.
// ---------------------------------------------------------------------------
__global__ __launch_bounds__(64)
void win_attn(const float* __restrict__ rpb)
{
    const int w = blockIdx.x;   // 0..4095
    const int h = blockIdx.y;   // 0..5
    const int t = threadIdx.x;  // 0..63 (query index in window)

    const int b  = w >> 10;
    const int wy = (w >> 5) & 31;
    const int wx = w & 31;
    const int ty = t >> 3;
    const int tx = t & 7;

    __shared__ float ks[WS2][HD];
    __shared__ float vs[WS2][HD];
    __shared__ float ps[WS2][WS2 + 1]; // padded: bank-conflict-free row access

    const size_t tok = (size_t)b * LTOK
                     + (size_t)(wy * WS + ty) * WIMG + (wx * WS + tx);
    const float* base = g_qkv + tok * QKVN + h * HD;

    const float scale = 0.17677669529663689f; // 1/sqrt(32)
    float q[HD];
    #pragma unroll
    for (int d = 0; d < HD; d += 4) {
        const float4 q4 = *reinterpret_cast<const float4*>(base + d);
        q[d + 0] = q4.x * scale; q[d + 1] = q4.y * scale;
        q[d + 2] = q4.z * scale; q[d + 3] = q4.w * scale;
        const float4 k4 = *reinterpret_cast<const float4*>(base + C + d);
        ks[t][d + 0] = k4.x; ks[t][d + 1] = k4.y;
        ks[t][d + 2] = k4.z; ks[t][d + 3] = k4.w;
        const float4 v4 = *reinterpret_cast<const float4*>(base + 2 * C + d);
        vs[t][d + 0] = v4.x; vs[t][d + 1] = v4.y;
        vs[t][d + 2] = v4.z; vs[t][d + 3] = v4.w;
    }
    __syncthreads();

    // scores + bias
    float mx = -1e30f;
    for (int j = 0; j < WS2; ++j) {
        const int ky = j >> 3, kx = j & 7;
        const int ridx = (ty - ky + WS - 1) * (2 * WS - 1) + (tx - kx + WS - 1);
        float acc = rpb[ridx * NH + h];
        #pragma unroll
        for (int d = 0; d < HD; ++d) acc += q[d] * ks[j][d];
        ps[t][j] = acc;
        mx = fmaxf(mx, acc);
    }
    // softmax
    float sum = 0.f;
    for (int j = 0; j < WS2; ++j) {
        const float e = __expf(ps[t][j] - mx);
        ps[t][j] = e;
        sum += e;
    }
    const float inv = 1.f / sum;

    // P @ V
    float o[HD] = {};
    for (int j = 0; j < WS2; ++j) {
        const float p = ps[t][j];
        #pragma unroll
        for (int d = 0; d < HD; ++d) o[d] += p * vs[j][d];
    }

    float* op = g_att + tok * C + h * HD;
    #pragma unroll
    for (int d = 0; d < HD; d += 4) {
        *reinterpret_cast<float4*>(op + d) =
            make_float4(o[d] * inv, o[d + 1] * inv, o[d + 2] * inv, o[d + 3] * inv);
    }
}

// ---------------------------------------------------------------------------
extern "C" void kernel_launch(void* const* d_in, const int* in_sizes, int n_in,
                              void* d_out, int out_size)
{
    (void)in_sizes; (void)n_in; (void)out_size;
    const float* x      = (const float*)d_in[0];
    const float* qkv_w  = (const float*)d_in[1];
    const float* proj_w = (const float*)d_in[2];
    const float* proj_b = (const float*)d_in[3];
    const float* rpb    = (const float*)d_in[4];
    float* out = (float*)d_out;

    float* qkv = nullptr;
    float* att = nullptr;
    cudaGetSymbolAddress((void**)&qkv, g_qkv);
    cudaGetSymbolAddress((void**)&att, g_att);

    // 1) QKV projection
    gemm_nt<64, 64, 16><<<dim3(QKVN / 64, MTOK / 64), 256>>>(
        x, qkv_w, nullptr, qkv, MTOK, QKVN, C);

    // 2) window attention
    win_attn<<<dim3(NWIN, NH), 64>>>(rpb);

    // 3) output projection + bias
    gemm_nt<64, 64, 16><<<dim3(C / 64, MTOK / 64), 256>>>(
        att, proj_w, proj_b, out, MTOK, C, C);
}

// round 2
// speedup vs baseline: 1.9333x; 1.9333x over previous
#include <cuda_runtime.h>
#include <cstdint>

// ---------------------------------------------------------------------------
// FastSpatialWindowAttention — Round 2: TF32 tensor-core GEMMs (mma.sync),
// fp32 window attention unchanged.
//   B=4, H=W=256, C=192, NH=6, hd=32, WS=8 (256 % 8 == 0 -> no padding)
// ---------------------------------------------------------------------------

namespace {
constexpr int BATCH = 4;
constexpr int HIMG  = 256;
constexpr int WIMG  = 256;
constexpr int C     = 192;
constexpr int NH    = 6;
constexpr int HD    = 32;
constexpr int WS    = 8;
constexpr int WS2   = 64;
constexpr int LTOK  = HIMG * WIMG;           // 65536
constexpr int MTOK  = BATCH * LTOK;          // 262144
constexpr int QKVN  = 3 * C;                 // 576
constexpr int NWIN  = BATCH * (HIMG / WS) * (WIMG / WS); // 4096

constexpr int BM = 128;
constexpr int BN = 64;
constexpr int BK = 16;
constexpr int SA = BK + 4;   // smem row stride (floats) -> conflict-spread, 16B aligned
}

// Scratch (allocation-free rule: static device globals)
__device__ float g_qkv[(size_t)MTOK * QKVN]; // 604 MB
__device__ float g_att[(size_t)MTOK * C];    // 201 MB

__device__ __forceinline__ uint32_t f2tf(float f) {
    uint32_t r;
    asm("cvt.rna.tf32.f32 %0, %1;" : "=r"(r) : "f"(f));
    return r;
}

__device__ __forceinline__ void mma_tf32(float c[4],
                                         uint32_t a0, uint32_t a1, uint32_t a2, uint32_t a3,
                                         uint32_t b0, uint32_t b1) {
    asm volatile(
        "mma.sync.aligned.m16n8k8.row.col.f32.tf32.tf32.f32 "
        "{%0,%1,%2,%3}, {%4,%5,%6,%7}, {%8,%9}, {%0,%1,%2,%3};"
        : "+f"(c[0]), "+f"(c[1]), "+f"(c[2]), "+f"(c[3])
        : "r"(a0), "r"(a1), "r"(a2), "r"(a3), "r"(b0), "r"(b1));
}

// ---------------------------------------------------------------------------
// C[M,N] = A[M,K] @ W[N,K]^T (+ bias), TF32 tensor cores.
// Block 128x64, BK=16, 256 threads = 8 warps (4 m x 2 n), warp tile 32x32.
// Per warp-tile: m16n8k8 mma, 2 m-tiles x 4 n-tiles x 2 k-steps per BK.
// ---------------------------------------------------------------------------
__global__ __launch_bounds__(256)
void gemm_tf32(const float* __restrict__ A,
               const float* __restrict__ W,
               const float* __restrict__ bias,
               float* __restrict__ Cout,
               int M, int N, int K)
{
    __shared__ uint32_t As[BM * SA];
    __shared__ uint32_t Bs[BN * SA];

    const int tid  = threadIdx.x;
    const int m0   = blockIdx.y * BM;
    const int n0   = blockIdx.x * BN;
    const int warp = tid >> 5;
    const int lane = tid & 31;
    const int wm   = (warp >> 1) * 32;  // warp m-offset within block
    const int wn   = (warp & 1) * 32;   // warp n-offset within block
    const int lr   = lane >> 2;         // 0..7
    const int lc   = lane & 3;          // 0..3

    float acc[2][4][4];
    #pragma unroll
    for (int mt = 0; mt < 2; ++mt)
        #pragma unroll
        for (int nt = 0; nt < 4; ++nt)
            #pragma unroll
            for (int i = 0; i < 4; ++i) acc[mt][nt][i] = 0.f;

    for (int k0 = 0; k0 < K; k0 += BK) {
        // Stage A tile (128x16): 2 float4 per thread
        #pragma unroll
        for (int i = 0; i < 2; ++i) {
            const int f  = tid + i * 256;
            const int r  = f >> 2;
            const int c4 = (f & 3) * 4;
            const float4 v = *reinterpret_cast<const float4*>(
                A + (size_t)(m0 + r) * K + k0 + c4);
            uint32_t* p = &As[r * SA + c4];
            p[0] = f2tf(v.x); p[1] = f2tf(v.y); p[2] = f2tf(v.z); p[3] = f2tf(v.w);
        }
        // Stage B tile (64x16): 1 float4 per thread
        {
            const int r  = tid >> 2;
            const int c4 = (tid & 3) * 4;
            const float4 v = *reinterpret_cast<const float4*>(
                W + (size_t)(n0 + r) * K + k0 + c4);
            uint32_t* p = &Bs[r * SA + c4];
            p[0] = f2tf(v.x); p[1] = f2tf(v.y); p[2] = f2tf(v.z); p[3] = f2tf(v.w);
        }
        __syncthreads();

        #pragma unroll
        for (int kk = 0; kk < BK; kk += 8) {
            uint32_t af[2][4], bf[4][2];
            #pragma unroll
            for (int mt = 0; mt < 2; ++mt) {
                const uint32_t* ap = &As[(wm + mt * 16 + lr) * SA + kk + lc];
                af[mt][0] = ap[0];
                af[mt][1] = ap[8 * SA];
                af[mt][2] = ap[4];
                af[mt][3] = ap[8 * SA + 4];
            }
            #pragma unroll
            for (int nt = 0; nt < 4; ++nt) {
                const uint32_t* bp = &Bs[(wn + nt * 8 + lr) * SA + kk + lc];
                bf[nt][0] = bp[0];
                bf[nt][1] = bp[4];
            }
            #pragma unroll
            for (int mt = 0; mt < 2; ++mt)
                #pragma unroll
                for (int nt = 0; nt < 4; ++nt)
                    mma_tf32(acc[mt][nt],
                             af[mt][0], af[mt][1], af[mt][2], af[mt][3],
                             bf[nt][0], bf[nt][1]);
        }
        __syncthreads();
    }

    // Epilogue: c0=(lr, 2lc), c1=(lr, 2lc+1), c2=(lr+8, 2lc), c3=(lr+8, 2lc+1)
    #pragma unroll
    for (int mt = 0; mt < 2; ++mt) {
        const int row0 = m0 + wm + mt * 16 + lr;
        #pragma unroll
        for (int nt = 0; nt < 4; ++nt) {
            const int col0 = n0 + wn + nt * 8 + 2 * lc;
            float2 v0 = make_float2(acc[mt][nt][0], acc[mt][nt][1]);
            float2 v1 = make_float2(acc[mt][nt][2], acc[mt][nt][3]);
            if (bias) {
                const float b0 = bias[col0], b1 = bias[col0 + 1];
                v0.x += b0; v0.y += b1;
                v1.x += b0; v1.y += b1;
            }
            *reinterpret_cast<float2*>(Cout + (size_t)row0 * N + col0)       = v0;
            *reinterpret_cast<float2*>(Cout + (size_t)(row0 + 8) * N + col0) = v1;
        }
    }
}

// ---------------------------------------------------------------------------
// Window attention: one block per (window, head), 64 threads = 1 per query row.
// ---------------------------------------------------------------------------
__global__ __launch_bounds__(64)
void win_attn(const float* __restrict__ rpb)
{
    const int w = blockIdx.x;
    const int h = blockIdx.y;
    const int t = threadIdx.x;

    const int b  = w >> 10;
    const int wy = (w >> 5) & 31;
    const int wx = w & 31;
    const int ty = t >> 3;
    const int tx = t & 7;

    __shared__ float ks[WS2][HD];
    __shared__ float vs[WS2][HD];
    __shared__ float ps[WS2][WS2 + 1];

    const size_t tok = (size_t)b * LTOK
                     + (size_t)(wy * WS + ty) * WIMG + (wx * WS + tx);
    const float* base = g_qkv + tok * QKVN + h * HD;

    const float scale = 0.17677669529663689f; // 1/sqrt(32)
    float q[HD];
    #pragma unroll
    for (int d = 0; d < HD; d += 4) {
        const float4 q4 = *reinterpret_cast<const float4*>(base + d);
        q[d + 0] = q4.x * scale; q[d + 1] = q4.y * scale;
        q[d + 2] = q4.z * scale; q[d + 3] = q4.w * scale;
        const float4 k4 = *reinterpret_cast<const float4*>(base + C + d);
        ks[t][d + 0] = k4.x; ks[t][d + 1] = k4.y;
        ks[t][d + 2] = k4.z; ks[t][d + 3] = k4.w;
        const float4 v4 = *reinterpret_cast<const float4*>(base + 2 * C + d);
        vs[t][d + 0] = v4.x; vs[t][d + 1] = v4.y;
        vs[t][d + 2] = v4.z; vs[t][d + 3] = v4.w;
    }
    __syncthreads();

    float mx = -1e30f;
    for (int j = 0; j < WS2; ++j) {
        const int ky = j >> 3, kx = j & 7;
        const int ridx = (ty - ky + WS - 1) * (2 * WS - 1) + (tx - kx + WS - 1);
        float acc = rpb[ridx * NH + h];
        #pragma unroll
        for (int d = 0; d < HD; ++d) acc += q[d] * ks[j][d];
        ps[t][j] = acc;
        mx = fmaxf(mx, acc);
    }
    float sum = 0.f;
    for (int j = 0; j < WS2; ++j) {
        const float e = __expf(ps[t][j] - mx);
        ps[t][j] = e;
        sum += e;
    }
    const float inv = 1.f / sum;

    float o[HD] = {};
    for (int j = 0; j < WS2; ++j) {
        const float p = ps[t][j];
        #pragma unroll
        for (int d = 0; d < HD; ++d) o[d] += p * vs[j][d];
    }

    float* op = g_att + tok * C + h * HD;
    #pragma unroll
    for (int d = 0; d < HD; d += 4) {
        *reinterpret_cast<float4*>(op + d) =
            make_float4(o[d] * inv, o[d + 1] * inv, o[d + 2] * inv, o[d + 3] * inv);
    }
}

// ---------------------------------------------------------------------------
extern "C" void kernel_launch(void* const* d_in, const int* in_sizes, int n_in,
                              void* d_out, int out_size)
{
    (void)in_sizes; (void)n_in; (void)out_size;
    const float* x      = (const float*)d_in[0];
    const float* qkv_w  = (const float*)d_in[1];
    const float* proj_w = (const float*)d_in[2];
    const float* proj_b = (const float*)d_in[3];
    const float* rpb    = (const float*)d_in[4];
    float* out = (float*)d_out;

    float* qkv = nullptr;
    float* att = nullptr;
    cudaGetSymbolAddress((void**)&qkv, g_qkv);
    cudaGetSymbolAddress((void**)&att, g_att);

    // 1) QKV projection (TF32 tensor cores)
    gemm_tf32<<<dim3(QKVN / BN, MTOK / BM), 256>>>(
        x, qkv_w, nullptr, qkv, MTOK, QKVN, C);

    // 2) window attention
    win_attn<<<dim3(NWIN, NH), 64>>>(rpb);

    // 3) output projection + bias (TF32 tensor cores)
    gemm_tf32<<<dim3(C / BN, MTOK / BM), 256>>>(
        att, proj_w, proj_b, out, MTOK, C, C);
}

// round 4
// speedup vs baseline: 2.3129x; 1.1963x over previous
#include <cuda_runtime.h>
#include <cstdint>

// ---------------------------------------------------------------------------
// FastSpatialWindowAttention — Round 4 (Round 3 + tokbase fix)
//   - TF32 mma GEMMs with permuted-k smem layout (LDS.64 fragment loads)
//   - Tensor-core window attention in 3xTF32 (fp32-accurate)
//   B=4, H=W=256, C=192, NH=6, hd=32, WS=8
// ---------------------------------------------------------------------------

namespace {
constexpr int HIMG  = 256;
constexpr int WIMG  = 256;
constexpr int C     = 192;
constexpr int NH    = 6;
constexpr int LTOK  = HIMG * WIMG;           // 65536
constexpr int MTOK  = 4 * LTOK;              // 262144
constexpr int QKVN  = 3 * C;                 // 576
constexpr int NWIN  = 4096;

constexpr int BM = 128;
constexpr int BN = 64;
constexpr int BK = 16;
constexpr int SA = 24;      // smem row stride in words (16 data + 8 pad)

// attention smem strides (words)
constexpr int QSTR = 40;    // 32-k buffers (q,k)
constexpr int PSTR = 72;    // 64-k buffers (p, vt)
}

__device__ float g_qkv[(size_t)MTOK * QKVN]; // 604 MB scratch
__device__ float g_att[(size_t)MTOK * C];    // 201 MB scratch

__device__ __forceinline__ uint32_t f2tf(float f) {
    uint32_t r;
    asm("cvt.rna.tf32.f32 %0, %1;" : "=r"(r) : "f"(f));
    return r;
}

__device__ __forceinline__ void mma_tf32(float c[4],
                                         uint32_t a0, uint32_t a1, uint32_t a2, uint32_t a3,
                                         uint32_t b0, uint32_t b1) {
    asm volatile(
        "mma.sync.aligned.m16n8k8.row.col.f32.tf32.tf32.f32 "
        "{%0,%1,%2,%3}, {%4,%5,%6,%7}, {%8,%9}, {%0,%1,%2,%3};"
        : "+f"(c[0]), "+f"(c[1]), "+f"(c[2]), "+f"(c[3])
        : "r"(a0), "r"(a1), "r"(a2), "r"(a3), "r"(b0), "r"(b1));
}

// permute within an 8-k group: pairs (k, k+4) become adjacent words
__device__ __forceinline__ int pc8(int k) { return ((k & 3) << 1) | ((k >> 2) & 1); }
__device__ __forceinline__ int pcN(int k) { return (k & ~7) | pc8(k & 7); }

// ---------------------------------------------------------------------------
// C[M,N] = A[M,K] @ W[N,K]^T (+ bias), TF32.  BM=128, BN=64, BK=16, 256 thr.
// ---------------------------------------------------------------------------
__global__ __launch_bounds__(256)
void gemm_tf32(const float* __restrict__ A,
               const float* __restrict__ W,
               const float* __restrict__ bias,
               float* __restrict__ Cout,
               int M, int N, int K)
{
    __shared__ uint32_t As[BM * SA];
    __shared__ uint32_t Bs[BN * SA];

    const int tid  = threadIdx.x;
    const int m0   = blockIdx.y * BM;
    const int n0   = blockIdx.x * BN;
    const int warp = tid >> 5;
    const int lane = tid & 31;
    const int wm   = (warp >> 1) * 32;
    const int wn   = (warp & 1) * 32;
    const int lr   = lane >> 2;
    const int lc   = lane & 3;

    const int ra  = tid >> 2;
    const int c4  = (tid & 3) * 4;
    const int gof = (c4 & 8) + ((c4 & 4) ? 1 : 0);

    float acc[2][4][4];
    #pragma unroll
    for (int mt = 0; mt < 2; ++mt)
        #pragma unroll
        for (int nt = 0; nt < 4; ++nt)
            #pragma unroll
            for (int i = 0; i < 4; ++i) acc[mt][nt][i] = 0.f;

    float4 pa0, pa1, pb;
    pa0 = *reinterpret_cast<const float4*>(A + (size_t)(m0 + ra) * K + c4);
    pa1 = *reinterpret_cast<const float4*>(A + (size_t)(m0 + 64 + ra) * K + c4);
    pb  = *reinterpret_cast<const float4*>(W + (size_t)(n0 + ra) * K + c4);

    for (int k0 = 0; k0 < K; k0 += BK) {
        {
            uint32_t* p = &As[ra * SA + gof];
            p[0] = f2tf(pa0.x); p[2] = f2tf(pa0.y); p[4] = f2tf(pa0.z); p[6] = f2tf(pa0.w);
            p = &As[(64 + ra) * SA + gof];
            p[0] = f2tf(pa1.x); p[2] = f2tf(pa1.y); p[4] = f2tf(pa1.z); p[6] = f2tf(pa1.w);
            p = &Bs[ra * SA + gof];
            p[0] = f2tf(pb.x);  p[2] = f2tf(pb.y);  p[4] = f2tf(pb.z);  p[6] = f2tf(pb.w);
        }
        __syncthreads();

        if (k0 + BK < K) {
            const int kn = k0 + BK + c4;
            pa0 = *reinterpret_cast<const float4*>(A + (size_t)(m0 + ra) * K + kn);
            pa1 = *reinterpret_cast<const float4*>(A + (size_t)(m0 + 64 + ra) * K + kn);
            pb  = *reinterpret_cast<const float4*>(W + (size_t)(n0 + ra) * K + kn);
        }

        #pragma unroll
        for (int kk = 0; kk < 2; ++kk) {
            const int ko = kk * 8 + 2 * lc;
            uint2 alo[2], ahi[2], bf[4];
            #pragma unroll
            for (int mt = 0; mt < 2; ++mt) {
                const int row = wm + mt * 16 + lr;
                alo[mt] = *reinterpret_cast<const uint2*>(&As[row * SA + ko]);
                ahi[mt] = *reinterpret_cast<const uint2*>(&As[(row + 8) * SA + ko]);
            }
            #pragma unroll
            for (int nt = 0; nt < 4; ++nt)
                bf[nt] = *reinterpret_cast<const uint2*>(&Bs[(wn + nt * 8 + lr) * SA + ko]);
            #pragma unroll
            for (int mt = 0; mt < 2; ++mt)
                #pragma unroll
                for (int nt = 0; nt < 4; ++nt)
                    mma_tf32(acc[mt][nt], alo[mt].x, ahi[mt].x, alo[mt].y, ahi[mt].y,
                             bf[nt].x, bf[nt].y);
        }
        __syncthreads();
    }

    #pragma unroll
    for (int mt = 0; mt < 2; ++mt) {
        const int row0 = m0 + wm + mt * 16 + lr;
        #pragma unroll
        for (int nt = 0; nt < 4; ++nt) {
            const int col0 = n0 + wn + nt * 8 + 2 * lc;
            float2 v0 = make_float2(acc[mt][nt][0], acc[mt][nt][1]);
            float2 v1 = make_float2(acc[mt][nt][2], acc[mt][nt][3]);
            if (bias) {
                const float b0 = bias[col0], b1 = bias[col0 + 1];
                v0.x += b0; v0.y += b1;
                v1.x += b0; v1.y += b1;
            }
            *reinterpret_cast<float2*>(Cout + (size_t)row0 * N + col0)       = v0;
            *reinterpret_cast<float2*>(Cout + (size_t)(row0 + 8) * N + col0) = v1;
        }
    }
}

// ---------------------------------------------------------------------------
// Window attention, tensor cores, 3xTF32. 256 threads, one window, 6 heads.
// ---------------------------------------------------------------------------
__global__ __launch_bounds__(256)
void win_attn(const float* __restrict__ rpb)
{
    extern __shared__ uint32_t sm[];
    uint32_t* qh  = sm;                        // 64*QSTR
    uint32_t* ql  = qh  + 64 * QSTR;
    uint32_t* kh  = ql  + 64 * QSTR;
    uint32_t* kl  = kh  + 64 * QSTR;
    uint32_t* vth = kl  + 64 * QSTR;           // 32*PSTR
    uint32_t* vtl = vth + 32 * PSTR;
    uint32_t* ph  = vtl + 32 * PSTR;           // 64*PSTR (aliased as fp32 S first)
    uint32_t* pl  = ph  + 64 * PSTR;
    float*    rpbs = (float*)(pl + 64 * PSTR); // 225*NH
    float*    rsum = rpbs + 225 * NH;          // 64
    float*    ss   = (float*)ph;

    const int tid  = threadIdx.x;
    const int warp = tid >> 5;
    const int lane = tid & 31;
    const int lr   = lane >> 2;
    const int lc   = lane & 3;

    const int w  = blockIdx.x;
    const int b  = w >> 10;
    const int wy = (w >> 5) & 31;
    const int wx = w & 31;
    // FIX (Round 3 bug): window row offset = wy * 8 rows of the image
    const size_t tokbase = (size_t)b * LTOK + (size_t)wy * 8 * WIMG + (size_t)wx * 8;

    for (int i = tid; i < 225 * NH; i += 256) rpbs[i] = rpb[i];

    const int ldtok = tid >> 2;       // 0..63
    const int part  = tid & 3;        // 0..3
    const size_t gtok = tokbase + (size_t)(ldtok >> 3) * WIMG + (ldtok & 7);
    const float* qp = g_qkv + gtok * QKVN;
    const float scale = 0.17677669529663689f;

    const int mt   = warp & 3;
    const int nh2  = warp >> 2;

    for (int h = 0; h < NH; ++h) {
        __syncthreads();

        // ---- load q,k,v head h -> smem (hi/lo tf32 split) ----
        {
            const float* pq = qp + h * 32 + part * 8;
            float4 u0 = *reinterpret_cast<const float4*>(pq);
            float4 u1 = *reinterpret_cast<const float4*>(pq + 4);
            float f[8] = {u0.x,u0.y,u0.z,u0.w,u1.x,u1.y,u1.z,u1.w};
            #pragma unroll
            for (int j = 0; j < 8; ++j) {
                const float v = f[j] * scale;
                const uint32_t hi = f2tf(v);
                const uint32_t lo = f2tf(v - __uint_as_float(hi));
                const int d = part * 8 + pc8(j) + ldtok * QSTR;
                qh[d] = hi; ql[d] = lo;
            }
            const float* pk = pq + C;
            u0 = *reinterpret_cast<const float4*>(pk);
            u1 = *reinterpret_cast<const float4*>(pk + 4);
            float g[8] = {u0.x,u0.y,u0.z,u0.w,u1.x,u1.y,u1.z,u1.w};
            #pragma unroll
            for (int j = 0; j < 8; ++j) {
                const uint32_t hi = f2tf(g[j]);
                const uint32_t lo = f2tf(g[j] - __uint_as_float(hi));
                const int d = part * 8 + pc8(j) + ldtok * QSTR;
                kh[d] = hi; kl[d] = lo;
            }
            const float* pv = pq + 2 * C;
            u0 = *reinterpret_cast<const float4*>(pv);
            u1 = *reinterpret_cast<const float4*>(pv + 4);
            float e[8] = {u0.x,u0.y,u0.z,u0.w,u1.x,u1.y,u1.z,u1.w};
            const int tperm = pcN(ldtok);
            #pragma unroll
            for (int j = 0; j < 8; ++j) {
                const uint32_t hi = f2tf(e[j]);
                const uint32_t lo = f2tf(e[j] - __uint_as_float(hi));
                const int d = (part * 8 + j) * PSTR + tperm;
                vth[d] = hi; vtl[d] = lo;
            }
        }
        __syncthreads();

        // ---- S = scale*Q K^T (3xTF32), warp tile 16x32 ----
        {
            float acc[4][4];
            #pragma unroll
            for (int nt = 0; nt < 4; ++nt)
                #pragma unroll
                for (int i = 0; i < 4; ++i) acc[nt][i] = 0.f;

            #pragma unroll
            for (int kk = 0; kk < 4; ++kk) {
                const int ko = kk * 8 + 2 * lc;
                const int r0 = (mt * 16 + lr) * QSTR + ko;
                const uint2 aho = *reinterpret_cast<const uint2*>(&qh[r0]);
                const uint2 ahi = *reinterpret_cast<const uint2*>(&qh[r0 + 8 * QSTR]);
                const uint2 alo = *reinterpret_cast<const uint2*>(&ql[r0]);
                const uint2 ali = *reinterpret_cast<const uint2*>(&ql[r0 + 8 * QSTR]);
                #pragma unroll
                for (int nt = 0; nt < 4; ++nt) {
                    const int kr = (nh2 * 32 + nt * 8 + lr) * QSTR + ko;
                    const uint2 bh = *reinterpret_cast<const uint2*>(&kh[kr]);
                    const uint2 bl = *reinterpret_cast<const uint2*>(&kl[kr]);
                    mma_tf32(acc[nt], aho.x, ahi.x, aho.y, ahi.y, bh.x, bh.y);
                    mma_tf32(acc[nt], aho.x, ahi.x, aho.y, ahi.y, bl.x, bl.y);
                    mma_tf32(acc[nt], alo.x, ali.x, alo.y, ali.y, bh.x, bh.y);
                }
            }
            #pragma unroll
            for (int nt = 0; nt < 4; ++nt) {
                #pragma unroll
                for (int e = 0; e < 4; ++e) {
                    const int r = mt * 16 + lr + (e >> 1) * 8;
                    const int c = nh2 * 32 + nt * 8 + 2 * lc + (e & 1);
                    const int ridx = ((r >> 3) - (c >> 3) + 7) * 15
                                   + ((r & 7) - (c & 7) + 7);
                    ss[r * PSTR + c] = acc[nt][e] + rpbs[ridx * NH + h];
                }
            }
        }
        __syncthreads();

        // ---- softmax rows (quad per row), write P hi/lo ----
        {
            const int row = tid >> 2;
            const int sub = tid & 3;
            float sv[16];
            float mx = -1e30f;
            #pragma unroll
            for (int j = 0; j < 16; ++j) {
                sv[j] = ss[row * PSTR + sub + 4 * j];
                mx = fmaxf(mx, sv[j]);
            }
            mx = fmaxf(mx, __shfl_xor_sync(0xffffffffu, mx, 1));
            mx = fmaxf(mx, __shfl_xor_sync(0xffffffffu, mx, 2));
            float sum = 0.f;
            #pragma unroll
            for (int j = 0; j < 16; ++j) {
                const float e = __expf(sv[j] - mx);
                sum += e;
                const uint32_t hi = f2tf(e);
                const uint32_t lo = f2tf(e - __uint_as_float(hi));
                const int c = sub + 4 * j;
                const int d = row * PSTR + pcN(c);
                ph[d] = hi; pl[d] = lo;
            }
            sum += __shfl_xor_sync(0xffffffffu, sum, 1);
            sum += __shfl_xor_sync(0xffffffffu, sum, 2);
            if (sub == 0) rsum[row] = 1.f / sum;
        }
        __syncthreads();

        // ---- O = P V (3xTF32), warp tile 16x16 over [64,32] ----
        {
            float acc[2][4];
            #pragma unroll
            for (int nt = 0; nt < 2; ++nt)
                #pragma unroll
                for (int i = 0; i < 4; ++i) acc[nt][i] = 0.f;

            #pragma unroll
            for (int kk = 0; kk < 8; ++kk) {
                const int ko = kk * 8 + 2 * lc;
                const int r0 = (mt * 16 + lr) * PSTR + ko;
                const uint2 aho = *reinterpret_cast<const uint2*>(&ph[r0]);
                const uint2 ahi = *reinterpret_cast<const uint2*>(&ph[r0 + 8 * PSTR]);
                const uint2 alo = *reinterpret_cast<const uint2*>(&pl[r0]);
                const uint2 ali = *reinterpret_cast<const uint2*>(&pl[r0 + 8 * PSTR]);
                #pragma unroll
                for (int nt = 0; nt < 2; ++nt) {
                    const int vr = (nh2 * 16 + nt * 8 + lr) * PSTR + ko;
                    const uint2 bh = *reinterpret_cast<const uint2*>(&vth[vr]);
                    const uint2 bl = *reinterpret_cast<const uint2*>(&vtl[vr]);
                    mma_tf32(acc[nt], aho.x, ahi.x, aho.y, ahi.y, bh.x, bh.y);
                    mma_tf32(acc[nt], aho.x, ahi.x, aho.y, ahi.y, bl.x, bl.y);
                    mma_tf32(acc[nt], alo.x, ali.x, alo.y, ali.y, bh.x, bh.y);
                }
            }
            #pragma unroll
            for (int nt = 0; nt < 2; ++nt) {
                #pragma unroll
                for (int e2 = 0; e2 < 2; ++e2) {
                    const int r = mt * 16 + lr + e2 * 8;
                    const float inv = rsum[r];
                    const int c = nh2 * 16 + nt * 8 + 2 * lc;
                    const size_t t = tokbase + (size_t)(r >> 3) * WIMG + (r & 7);
                    float2 v = make_float2(acc[nt][e2 * 2] * inv, acc[nt][e2 * 2 + 1] * inv);
                    *reinterpret_cast<float2*>(g_att + t * C + h * 32 + c) = v;
                }
            }
        }
    }
}

// ---------------------------------------------------------------------------
extern "C" void kernel_launch(void* const* d_in, const int* in_sizes, int n_in,
                              void* d_out, int out_size)
{
    (void)in_sizes; (void)n_in; (void)out_size;
    const float* x      = (const float*)d_in[0];
    const float* qkv_w  = (const float*)d_in[1];
    const float* proj_w = (const float*)d_in[2];
    const float* proj_b = (const float*)d_in[3];
    const float* rpb    = (const float*)d_in[4];
    float* out = (float*)d_out;

    float* qkv = nullptr;
    float* att = nullptr;
    cudaGetSymbolAddress((void**)&qkv, g_qkv);
    cudaGetSymbolAddress((void**)&att, g_att);

    const int attn_smem = (4 * 64 * QSTR + 2 * 32 * PSTR + 2 * 64 * PSTR
                           + 225 * NH + 64) * 4;
    cudaFuncSetAttribute(win_attn, cudaFuncAttributeMaxDynamicSharedMemorySize,
                         attn_smem);

    gemm_tf32<<<dim3(QKVN / BN, MTOK / BM), 256>>>(
        x, qkv_w, nullptr, qkv, MTOK, QKVN, C);

    win_attn<<<NWIN, 256, attn_smem>>>(rpb);

    gemm_tf32<<<dim3(C / BN, MTOK / BM), 256>>>(
        att, proj_w, proj_b, out, MTOK, C, C);
}

// round 6
// speedup vs baseline: 2.8006x; 1.2109x over previous
#include <cuda_runtime.h>
#include <cstdint>

// ---------------------------------------------------------------------------
// FastSpatialWindowAttention — Round 6 (Round 5 resubmit; infra failure)
//   - TF32 GEMM: BM=256 BN=64 BK=16, warp tile 64x32, double-buffered smem,
//     single sync per K-tile, vector STS staging, natural k layout.
//   - Window attention: unchanged from Round 4 (3xTF32 tensor cores).
// ---------------------------------------------------------------------------

namespace {
constexpr int HIMG  = 256;
constexpr int WIMG  = 256;
constexpr int C     = 192;
constexpr int NH    = 6;
constexpr int LTOK  = HIMG * WIMG;           // 65536
constexpr int MTOK  = 4 * LTOK;              // 262144
constexpr int QKVN  = 3 * C;                 // 576
constexpr int NWIN  = 4096;

constexpr int BM = 256;
constexpr int BN = 64;
constexpr int BK = 16;
constexpr int SA = 20;      // smem row stride words (16 data + 4 pad) — conflict-free

// attention smem strides (words)
constexpr int QSTR = 40;
constexpr int PSTR = 72;
}

__device__ float g_qkv[(size_t)MTOK * QKVN]; // 604 MB scratch
__device__ float g_att[(size_t)MTOK * C];    // 201 MB scratch

__device__ __forceinline__ uint32_t f2tf(float f) {
    uint32_t r;
    asm("cvt.rna.tf32.f32 %0, %1;" : "=r"(r) : "f"(f));
    return r;
}

__device__ __forceinline__ void mma_tf32(float c[4],
                                         uint32_t a0, uint32_t a1, uint32_t a2, uint32_t a3,
                                         uint32_t b0, uint32_t b1) {
    asm volatile(
        "mma.sync.aligned.m16n8k8.row.col.f32.tf32.tf32.f32 "
        "{%0,%1,%2,%3}, {%4,%5,%6,%7}, {%8,%9}, {%0,%1,%2,%3};"
        : "+f"(c[0]), "+f"(c[1]), "+f"(c[2]), "+f"(c[3])
        : "r"(a0), "r"(a1), "r"(a2), "r"(a3), "r"(b0), "r"(b1));
}

// attention helpers
__device__ __forceinline__ int pc8(int k) { return ((k & 3) << 1) | ((k >> 2) & 1); }
__device__ __forceinline__ int pcN(int k) { return (k & ~7) | pc8(k & 7); }

// ---------------------------------------------------------------------------
// C[M,N] = A[M,K] @ W[N,K]^T (+ bias), TF32.
// BM=256, BN=64, BK=16. 256 threads = 8 warps (4m x 2n), warp tile 64x32.
// Double-buffered smem, one __syncthreads per K-tile.
// ---------------------------------------------------------------------------
__global__ __launch_bounds__(256, 2)
void gemm_tf32(const float* __restrict__ A,
               const float* __restrict__ W,
               const float* __restrict__ bias,
               float* __restrict__ Cout,
               int M, int N, int K)
{
    extern __shared__ uint32_t smem[];
    uint32_t* As = smem;                 // 2 buffers of BM*SA
    uint32_t* Bs = smem + 2 * BM * SA;   // 2 buffers of BN*SA

    const int tid  = threadIdx.x;
    const int m0   = blockIdx.y * BM;
    const int n0   = blockIdx.x * BN;
    const int warp = tid >> 5;
    const int lane = tid & 31;
    const int wm   = (warp >> 1) * 64;   // 4 m-warps
    const int wn   = (warp & 1) * 32;    // 2 n-warps
    const int lr   = lane >> 2;
    const int lc   = lane & 3;

    const int ra  = tid >> 2;            // 0..63
    const int c4  = (tid & 3) * 4;       // 0,4,8,12

    float acc[4][4][4];
    #pragma unroll
    for (int mt = 0; mt < 4; ++mt)
        #pragma unroll
        for (int nt = 0; nt < 4; ++nt)
            #pragma unroll
            for (int i = 0; i < 4; ++i) acc[mt][nt][i] = 0.f;

    const int ntiles = K / BK;

    // prefetch registers
    float4 pa[4], pb;
    #pragma unroll
    for (int i = 0; i < 4; ++i)
        pa[i] = *reinterpret_cast<const float4*>(A + (size_t)(m0 + ra + i * 64) * K + c4);
    pb = *reinterpret_cast<const float4*>(W + (size_t)(n0 + ra) * K + c4);

    // store tile 0 into buffer 0
    {
        #pragma unroll
        for (int i = 0; i < 4; ++i) {
            uint4 s = make_uint4(f2tf(pa[i].x), f2tf(pa[i].y), f2tf(pa[i].z), f2tf(pa[i].w));
            *reinterpret_cast<uint4*>(&As[(ra + i * 64) * SA + c4]) = s;
        }
        uint4 s = make_uint4(f2tf(pb.x), f2tf(pb.y), f2tf(pb.z), f2tf(pb.w));
        *reinterpret_cast<uint4*>(&Bs[ra * SA + c4]) = s;
    }
    __syncthreads();

    for (int t = 0; t < ntiles; ++t) {
        const uint32_t* Ac = As + (t & 1) * BM * SA;
        const uint32_t* Bc = Bs + (t & 1) * BN * SA;

        // prefetch next tile from gmem
        if (t + 1 < ntiles) {
            const int kn = (t + 1) * BK + c4;
            #pragma unroll
            for (int i = 0; i < 4; ++i)
                pa[i] = *reinterpret_cast<const float4*>(A + (size_t)(m0 + ra + i * 64) * K + kn);
            pb = *reinterpret_cast<const float4*>(W + (size_t)(n0 + ra) * K + kn);
        }

        // MMA over current buffer
        #pragma unroll
        for (int kk = 0; kk < BK; kk += 8) {
            const int ko = kk + lc;
            uint32_t af[4][4], bf[4][2];
            #pragma unroll
            for (int mt = 0; mt < 4; ++mt) {
                const uint32_t* ap = &Ac[(wm + mt * 16 + lr) * SA + ko];
                af[mt][0] = ap[0];
                af[mt][1] = ap[8 * SA];
                af[mt][2] = ap[4];
                af[mt][3] = ap[8 * SA + 4];
            }
            #pragma unroll
            for (int nt = 0; nt < 4; ++nt) {
                const uint32_t* bp = &Bc[(wn + nt * 8 + lr) * SA + ko];
                bf[nt][0] = bp[0];
                bf[nt][1] = bp[4];
            }
            #pragma unroll
            for (int mt = 0; mt < 4; ++mt)
                #pragma unroll
                for (int nt = 0; nt < 4; ++nt)
                    mma_tf32(acc[mt][nt], af[mt][0], af[mt][1], af[mt][2], af[mt][3],
                             bf[nt][0], bf[nt][1]);
        }

        // store next tile into the other buffer (disjoint from current reads)
        if (t + 1 < ntiles) {
            uint32_t* An = As + ((t + 1) & 1) * BM * SA;
            uint32_t* Bn = Bs + ((t + 1) & 1) * BN * SA;
            #pragma unroll
            for (int i = 0; i < 4; ++i) {
                uint4 s = make_uint4(f2tf(pa[i].x), f2tf(pa[i].y), f2tf(pa[i].z), f2tf(pa[i].w));
                *reinterpret_cast<uint4*>(&An[(ra + i * 64) * SA + c4]) = s;
            }
            uint4 s = make_uint4(f2tf(pb.x), f2tf(pb.y), f2tf(pb.z), f2tf(pb.w));
            *reinterpret_cast<uint4*>(&Bn[ra * SA + c4]) = s;
        }
        __syncthreads();
    }

    #pragma unroll
    for (int mt = 0; mt < 4; ++mt) {
        const int row0 = m0 + wm + mt * 16 + lr;
        #pragma unroll
        for (int nt = 0; nt < 4; ++nt) {
            const int col0 = n0 + wn + nt * 8 + 2 * lc;
            float2 v0 = make_float2(acc[mt][nt][0], acc[mt][nt][1]);
            float2 v1 = make_float2(acc[mt][nt][2], acc[mt][nt][3]);
            if (bias) {
                const float b0 = bias[col0], b1 = bias[col0 + 1];
                v0.x += b0; v0.y += b1;
                v1.x += b0; v1.y += b1;
            }
            *reinterpret_cast<float2*>(Cout + (size_t)row0 * N + col0)       = v0;
            *reinterpret_cast<float2*>(Cout + (size_t)(row0 + 8) * N + col0) = v1;
        }
    }
}

// ---------------------------------------------------------------------------
// Window attention, tensor cores, 3xTF32 (unchanged from Round 4).
// ---------------------------------------------------------------------------
__global__ __launch_bounds__(256)
void win_attn(const float* __restrict__ rpb)
{
    extern __shared__ uint32_t sm[];
    uint32_t* qh  = sm;
    uint32_t* ql  = qh  + 64 * QSTR;
    uint32_t* kh  = ql  + 64 * QSTR;
    uint32_t* kl  = kh  + 64 * QSTR;
    uint32_t* vth = kl  + 64 * QSTR;
    uint32_t* vtl = vth + 32 * PSTR;
    uint32_t* ph  = vtl + 32 * PSTR;
    uint32_t* pl  = ph  + 64 * PSTR;
    float*    rpbs = (float*)(pl + 64 * PSTR);
    float*    rsum = rpbs + 225 * NH;
    float*    ss   = (float*)ph;

    const int tid  = threadIdx.x;
    const int warp = tid >> 5;
    const int lane = tid & 31;
    const int lr   = lane >> 2;
    const int lc   = lane & 3;

    const int w  = blockIdx.x;
    const int b  = w >> 10;
    const int wy = (w >> 5) & 31;
    const int wx = w & 31;
    const size_t tokbase = (size_t)b * LTOK + (size_t)wy * 8 * WIMG + (size_t)wx * 8;

    for (int i = tid; i < 225 * NH; i += 256) rpbs[i] = rpb[i];

    const int ldtok = tid >> 2;
    const int part  = tid & 3;
    const size_t gtok = tokbase + (size_t)(ldtok >> 3) * WIMG + (ldtok & 7);
    const float* qp = g_qkv + gtok * QKVN;
    const float scale = 0.17677669529663689f;

    const int mt   = warp & 3;
    const int nh2  = warp >> 2;

    for (int h = 0; h < NH; ++h) {
        __syncthreads();

        {
            const float* pq = qp + h * 32 + part * 8;
            float4 u0 = *reinterpret_cast<const float4*>(pq);
            float4 u1 = *reinterpret_cast<const float4*>(pq + 4);
            float f[8] = {u0.x,u0.y,u0.z,u0.w,u1.x,u1.y,u1.z,u1.w};
            #pragma unroll
            for (int j = 0; j < 8; ++j) {
                const float v = f[j] * scale;
                const uint32_t hi = f2tf(v);
                const uint32_t lo = f2tf(v - __uint_as_float(hi));
                const int d = part * 8 + pc8(j) + ldtok * QSTR;
                qh[d] = hi; ql[d] = lo;
            }
            const float* pk = pq + C;
            u0 = *reinterpret_cast<const float4*>(pk);
            u1 = *reinterpret_cast<const float4*>(pk + 4);
            float g[8] = {u0.x,u0.y,u0.z,u0.w,u1.x,u1.y,u1.z,u1.w};
            #pragma unroll
            for (int j = 0; j < 8; ++j) {
                const uint32_t hi = f2tf(g[j]);
                const uint32_t lo = f2tf(g[j] - __uint_as_float(hi));
                const int d = part * 8 + pc8(j) + ldtok * QSTR;
                kh[d] = hi; kl[d] = lo;
            }
            const float* pv = pq + 2 * C;
            u0 = *reinterpret_cast<const float4*>(pv);
            u1 = *reinterpret_cast<const float4*>(pv + 4);
            float e[8] = {u0.x,u0.y,u0.z,u0.w,u1.x,u1.y,u1.z,u1.w};
            const int tperm = pcN(ldtok);
            #pragma unroll
            for (int j = 0; j < 8; ++j) {
                const uint32_t hi = f2tf(e[j]);
                const uint32_t lo = f2tf(e[j] - __uint_as_float(hi));
                const int d = (part * 8 + j) * PSTR + tperm;
                vth[d] = hi; vtl[d] = lo;
            }
        }
        __syncthreads();

        {
            float acc[4][4];
            #pragma unroll
            for (int nt = 0; nt < 4; ++nt)
                #pragma unroll
                for (int i = 0; i < 4; ++i) acc[nt][i] = 0.f;

            #pragma unroll
            for (int kk = 0; kk < 4; ++kk) {
                const int ko = kk * 8 + 2 * lc;
                const int r0 = (mt * 16 + lr) * QSTR + ko;
                const uint2 aho = *reinterpret_cast<const uint2*>(&qh[r0]);
                const uint2 ahi = *reinterpret_cast<const uint2*>(&qh[r0 + 8 * QSTR]);
                const uint2 alo = *reinterpret_cast<const uint2*>(&ql[r0]);
                const uint2 ali = *reinterpret_cast<const uint2*>(&ql[r0 + 8 * QSTR]);
                #pragma unroll
                for (int nt = 0; nt < 4; ++nt) {
                    const int kr = (nh2 * 32 + nt * 8 + lr) * QSTR + ko;
                    const uint2 bh = *reinterpret_cast<const uint2*>(&kh[kr]);
                    const uint2 bl = *reinterpret_cast<const uint2*>(&kl[kr]);
                    mma_tf32(acc[nt], aho.x, ahi.x, aho.y, ahi.y, bh.x, bh.y);
                    mma_tf32(acc[nt], aho.x, ahi.x, aho.y, ahi.y, bl.x, bl.y);
                    mma_tf32(acc[nt], alo.x, ali.x, alo.y, ali.y, bh.x, bh.y);
                }
            }
            #pragma unroll
            for (int nt = 0; nt < 4; ++nt) {
                #pragma unroll
                for (int e = 0; e < 4; ++e) {
                    const int r = mt * 16 + lr + (e >> 1) * 8;
                    const int c = nh2 * 32 + nt * 8 + 2 * lc + (e & 1);
                    const int ridx = ((r >> 3) - (c >> 3) + 7) * 15
                                   + ((r & 7) - (c & 7) + 7);
                    ss[r * PSTR + c] = acc[nt][e] + rpbs[ridx * NH + h];
                }
            }
        }
        __syncthreads();

        {
            const int row = tid >> 2;
            const int sub = tid & 3;
            float sv[16];
            float mx = -1e30f;
            #pragma unroll
            for (int j = 0; j < 16; ++j) {
                sv[j] = ss[row * PSTR + sub + 4 * j];
                mx = fmaxf(mx, sv[j]);
            }
            mx = fmaxf(mx, __shfl_xor_sync(0xffffffffu, mx, 1));
            mx = fmaxf(mx, __shfl_xor_sync(0xffffffffu, mx, 2));
            float sum = 0.f;
            #pragma unroll
            for (int j = 0; j < 16; ++j) {
                const float e = __expf(sv[j] - mx);
                sum += e;
                const uint32_t hi = f2tf(e);
                const uint32_t lo = f2tf(e - __uint_as_float(hi));
                const int c = sub + 4 * j;
                const int d = row * PSTR + pcN(c);
                ph[d] = hi; pl[d] = lo;
            }
            sum += __shfl_xor_sync(0xffffffffu, sum, 1);
            sum += __shfl_xor_sync(0xffffffffu, sum, 2);
            if (sub == 0) rsum[row] = 1.f / sum;
        }
        __syncthreads();

        {
            float acc[2][4];
            #pragma unroll
            for (int nt = 0; nt < 2; ++nt)
                #pragma unroll
                for (int i = 0; i < 4; ++i) acc[nt][i] = 0.f;

            #pragma unroll
            for (int kk = 0; kk < 8; ++kk) {
                const int ko = kk * 8 + 2 * lc;
                const int r0 = (mt * 16 + lr) * PSTR + ko;
                const uint2 aho = *reinterpret_cast<const uint2*>(&ph[r0]);
                const uint2 ahi = *reinterpret_cast<const uint2*>(&ph[r0 + 8 * PSTR]);
                const uint2 alo = *reinterpret_cast<const uint2*>(&pl[r0]);
                const uint2 ali = *reinterpret_cast<const uint2*>(&pl[r0 + 8 * PSTR]);
                #pragma unroll
                for (int nt = 0; nt < 2; ++nt) {
                    const int vr = (nh2 * 16 + nt * 8 + lr) * PSTR + ko;
                    const uint2 bh = *reinterpret_cast<const uint2*>(&vth[vr]);
                    const uint2 bl = *reinterpret_cast<const uint2*>(&vtl[vr]);
                    mma_tf32(acc[nt], aho.x, ahi.x, aho.y, ahi.y, bh.x, bh.y);
                    mma_tf32(acc[nt], aho.x, ahi.x, aho.y, ahi.y, bl.x, bl.y);
                    mma_tf32(acc[nt], alo.x, ali.x, alo.y, ali.y, bh.x, bh.y);
                }
            }
            #pragma unroll
            for (int nt = 0; nt < 2; ++nt) {
                #pragma unroll
                for (int e2 = 0; e2 < 2; ++e2) {
                    const int r = mt * 16 + lr + e2 * 8;
                    const float inv = rsum[r];
                    const int c = nh2 * 16 + nt * 8 + 2 * lc;
                    const size_t t = tokbase + (size_t)(r >> 3) * WIMG + (r & 7);
                    float2 v = make_float2(acc[nt][e2 * 2] * inv, acc[nt][e2 * 2 + 1] * inv);
                    *reinterpret_cast<float2*>(g_att + t * C + h * 32 + c) = v;
                }
            }
        }
    }
}

// ---------------------------------------------------------------------------
extern "C" void kernel_launch(void* const* d_in, const int* in_sizes, int n_in,
                              void* d_out, int out_size)
{
    (void)in_sizes; (void)n_in; (void)out_size;
    const float* x      = (const float*)d_in[0];
    const float* qkv_w  = (const float*)d_in[1];
    const float* proj_w = (const float*)d_in[2];
    const float* proj_b = (const float*)d_in[3];
    const float* rpb    = (const float*)d_in[4];
    float* out = (float*)d_out;

    float* qkv = nullptr;
    float* att = nullptr;
    cudaGetSymbolAddress((void**)&qkv, g_qkv);
    cudaGetSymbolAddress((void**)&att, g_att);

    const int gemm_smem = 2 * (BM + BN) * SA * 4;   // 51200 B
    cudaFuncSetAttribute(gemm_tf32, cudaFuncAttributeMaxDynamicSharedMemorySize,
                         gemm_smem);

    const int attn_smem = (4 * 64 * QSTR + 2 * 32 * PSTR + 2 * 64 * PSTR
                           + 225 * NH + 64) * 4;
    cudaFuncSetAttribute(win_attn, cudaFuncAttributeMaxDynamicSharedMemorySize,
                         attn_smem);

    gemm_tf32<<<dim3(QKVN / BN, MTOK / BM), 256, gemm_smem>>>(
        x, qkv_w, nullptr, qkv, MTOK, QKVN, C);

    win_attn<<<NWIN, 256, attn_smem>>>(rpb);

    gemm_tf32<<<dim3(C / BN, MTOK / BM), 256, gemm_smem>>>(
        att, proj_w, proj_b, out, MTOK, C, C);
}